// round 16
// baseline (speedup 1.0000x reference)
#include <cuda_runtime.h>
#include <math.h>

typedef unsigned long long u64;

#define FMA2(d, a, b, c) \
    asm("fma.rn.f32x2 %0, %1, %2, %3;" : "=l"(d) : "l"(a), "l"(b), "l"(c))
#define PACK2(d, lo, hi) \
    asm("mov.b64 %0, {%1, %2};" : "=l"(d) : "f"(lo), "f"(hi))
#define UNPACK2(lo, hi, d) \
    asm("mov.b64 {%0, %1}, %2;" : "=f"(lo), "=f"(hi) : "l"(d))
#define LDS_V2B64(a, b, addr) \
    asm volatile("ld.shared.v2.b64 {%0, %1}, [%2];" : "=l"(a), "=l"(b) : "r"(addr))
#define CVT_TF32(u, f) \
    asm("cvt.rna.tf32.f32 %0, %1;" : "=r"(u) : "f"(f))
#define MMA_TF32(d, a0, a1, a2, a3, b0, b1) \
    asm("mma.sync.aligned.m16n8k8.row.col.f32.tf32.tf32.f32 " \
        "{%0,%1,%2,%3},{%4,%5,%6,%7},{%8,%9},{%0,%1,%2,%3};" \
        : "+f"(d[0]), "+f"(d[1]), "+f"(d[2]), "+f"(d[3]) \
        : "r"(a0), "r"(a1), "r"(a2), "r"(a3), "r"(b0), "r"(b1))

#define N_IN   4096
#define N_OUT  1024
#define BATCH  16
#define E_MAX  81920

__device__ float g_featT2[N_IN * 512];                 // [n][c*16+b]
__device__ float g_W3t[65536];                         // tf32 fragment-ordered W3
__device__ int   g_seg[E_MAX];
__device__ int   g_src[E_MAX];

// ---------------- phase -1: idx normalize + zero output (one kernel) --------
__global__ void prep_idx(const int* __restrict__ idx32,
                         float4* __restrict__ out4, int E) {
    int local = 0;
    int n = min(E, 512);
    for (int m = threadIdx.x; m < n; m += 256)
        local |= idx32[4 * m + 1] | idx32[4 * m + 3];
    int any32 = __syncthreads_or(local);
    int m = blockIdx.x * 256 + threadIdx.x;
    if (m < E) {
        if (any32) { g_seg[m] = idx32[2 * m]; g_src[m] = idx32[2 * m + 1]; }
        else       { g_seg[m] = idx32[4 * m]; g_src[m] = idx32[4 * m + 2]; }
    }
    if (m < (BATCH * 32 * N_OUT) / 4)
        out4[m] = make_float4(0.f, 0.f, 0.f, 0.f);
}

// ---------------- phase -0.8: W3 -> tf32 fragment-ordered copy --------------
__global__ void prep_w3t(const float* __restrict__ W3) {
    int i = blockIdx.x * 256 + threadIdx.x;   // 0..65535
    int ks  = i >> 13;
    int rem = i & 8191;
    int gt  = rem >> 6;
    int q   = rem & 63;
    int l   = q >> 1, h = q & 1;
    float v = W3[(ks * 8 + (l & 3) + 4 * h) * 1024 + gt * 8 + (l >> 2)];
    unsigned u; CVT_TF32(u, v);
    g_W3t[i] = __uint_as_float(u);
}

// ---------------- phase 0: tiled permute feat[b][c][n] -> featT2[n][c*16+b]
__global__ void prep_featT(const float* __restrict__ feat) {
    __shared__ float tile[32][33];
    int n0  = blockIdx.x * 32;
    int cb0 = blockIdx.y * 32;
    int tx = threadIdx.x, ty = threadIdx.y;       // 32 x 8
    #pragma unroll
    for (int i = ty; i < 32; i += 8) {
        int cb = cb0 + i;
        int row = (cb & 15) * 32 + (cb >> 4);     // b*32 + c
        tile[i][tx] = feat[(size_t)row * N_IN + n0 + tx];
    }
    __syncthreads();
    #pragma unroll
    for (int i = ty; i < 32; i += 8)
        g_featT2[(size_t)(n0 + i) * 512 + cb0 + tx] = tile[tx][i];
}

// ---------------- phase A ----------------------------------------------------
// 512 threads, 16 edges/block, 2 blocks/SM. smem (floats):
//  h1 [16][65]     @0      (1040)
//  h2e[16][68]     @1040   (1088)
//  W2s[64][64]     @2128   (4096)
//  g  [8][16][36]  @6224   (4608)   <- overlaid by vals[16][264] after apply
//  filt[8][32][36] @10832  (9216)
//  locs[64]        @20048
//  goff[512] int   @20112
//  keys[512] int   @20624
//  gstart[2][66]+ng[2] int @21136
#define OFF_H1   0
#define OFF_H2E  1040
#define OFF_W2S  2128
#define OFF_G    6224
#define OFF_F    10832
#define OFF_LOCS 20048
#define OFF_GOFF 20112
#define OFF_KEYS 20624
#define OFF_GST  21136
#define SMEM_A_FLOATS 21272
#define SMEM_A_BYTES  (SMEM_A_FLOATS * 4)
#define VROW 264

__global__ __launch_bounds__(512, 2) void quad_main(
    const float* __restrict__ W1, const float* __restrict__ W2,
    const float* __restrict__ eval_locs, float* __restrict__ out, int E)
{
    extern __shared__ float sm[];
    float* h1_s   = sm + OFF_H1;
    float* h2e    = sm + OFF_H2E;
    float* W2s    = sm + OFF_W2S;
    float* g_s    = sm + OFF_G;
    float* vals_s = sm + OFF_G;        // overlay after apply
    float* f_s    = sm + OFF_F;
    float* locs   = sm + OFF_LOCS;
    int*   goff   = (int*)(sm + OFF_GOFF);
    int*   keys_s = (int*)(sm + OFF_KEYS);
    int*   gst    = (int*)(sm + OFF_GST);       // [2][66]
    int*   ng_s   = (int*)(sm + OFF_GST) + 132; // [2]
    const unsigned smb = (unsigned)__cvta_generic_to_shared(sm);

    const int t   = threadIdx.x;
    const int e0  = blockIdx.x * 16;
    const int net = min(16, E - e0);
    const int mb  = blockIdx.x * 512;   // flat vals base for this block

    if (t < 2 * net) locs[t] = eval_locs[2 * e0 + t];

    // stage W2 into smem (coalesced, once per block)
    #pragma unroll
    for (int r = 0; r < 8; r++)
        W2s[t + 512 * r] = W2[t + 512 * r];

    // gather offsets per (e, ci) AND scramble keys per flat pos p
    {
        int p = t;                        // 0..511
        int key = -1;
        if (p < net * 32) {
            int m  = mb + p;
            int c  = m / E;
            int rr = m - c * E;
            goff[p] = g_src[rr] * 512 + c * 16;
            key = (c << 10) + g_seg[rr];
        }
        keys_s[p] = key;
    }
    __syncthreads();

    // warps 0/1: run-boundary scan of keys for sub 0/1
    if (t < 64) {
        int sub  = t >> 5, l = t & 31;
        int base = sub * 256;
        int cnt = 0, st[8];
        #pragma unroll
        for (int i = 0; i < 8; i++) {
            int p = base + l * 8 + i;
            int kprev = (p == base) ? 0x7fffffff : keys_s[p - 1];
            if (keys_s[p] != kprev) st[cnt++] = p;
        }
        unsigned off = (unsigned)cnt;
        #pragma unroll
        for (int d = 1; d < 32; d <<= 1) {
            unsigned v = __shfl_up_sync(0xffffffffu, off, d);
            if (l >= d) off += v;
        }
        int excl = (int)off - cnt;
        for (int i = 0; i < cnt; i++) gst[sub * 66 + excl + i] = st[i];
        if (l == 31) { ng_s[sub] = (int)off; gst[sub * 66 + (int)off] = base + 256; }
    }

    // h1[e][j] = sin(loc_e . W1[:,j])   (0 for padded edges); pad-65 rows
    #pragma unroll
    for (int r = 0; r < 2; r++) {
        int id = t + 512 * r;             // 0..1023
        int e = id >> 6, j = id & 63;
        float v = 0.f;
        if (e < net)
            v = __sinf(locs[2 * e] * W1[j] + locs[2 * e + 1] * W1[64 + j]);
        h1_s[e * 65 + j] = v;
    }
    __syncthreads();

    // ---- h2 (f32x2): 128 threads, thread owns (e = t>>3, 8 cols j0=(t&7)*8)
    if (t < 128) {
        const int e  = t >> 3;
        const int j0 = (t & 7) * 8;
        u64 acc[4] = {0ull, 0ull, 0ull, 0ull};
        #pragma unroll 8
        for (int k = 0; k < 64; k++) {
            float hv = h1_s[e * 65 + k];
            u64 hh; PACK2(hh, hv, hv);
            const unsigned wa = smb + (OFF_W2S + k * 64 + j0) * 4;
            u64 w0, w1, w2v, w3v;
            LDS_V2B64(w0, w1, wa);
            LDS_V2B64(w2v, w3v, wa + 16);
            FMA2(acc[0], hh, w0, acc[0]);
            FMA2(acc[1], hh, w1, acc[1]);
            FMA2(acc[2], hh, w2v, acc[2]);
            FMA2(acc[3], hh, w3v, acc[3]);
        }
        float s[8];
        UNPACK2(s[0], s[1], acc[0]);
        UNPACK2(s[2], s[3], acc[1]);
        UNPACK2(s[4], s[5], acc[2]);
        UNPACK2(s[6], s[7], acc[3]);
        #pragma unroll
        for (int i = 0; i < 8; i++) s[i] = (e < net) ? __sinf(s[i]) : 0.f;
        *(float4*)&h2e[e * 68 + j0]     = make_float4(s[0], s[1], s[2], s[3]);
        *(float4*)&h2e[e * 68 + j0 + 4] = make_float4(s[4], s[5], s[6], s[7]);
    }
    __syncthreads();

    // ---- filter gen on tensor cores (tf32 mma.sync m16n8k8) ----
    // warp w (0..15) owns cols [w*64, w*64+64): 8 n-tiles x 8 k-steps.
    const int lane = t & 31;
    const int w    = t >> 5;
    const int rA   = lane >> 2;
    const int tig  = lane & 3;

    float dacc[8][4];
    #pragma unroll
    for (int ti = 0; ti < 8; ti++) {
        dacc[ti][0] = 0.f; dacc[ti][1] = 0.f;
        dacc[ti][2] = 0.f; dacc[ti][3] = 0.f;
    }

    #pragma unroll
    for (int ks = 0; ks < 8; ks++) {
        const int kk = ks * 8 + tig;
        unsigned A0, A1, A2, A3;
        CVT_TF32(A0, h2e[rA * 68 + kk]);
        CVT_TF32(A1, h2e[(rA + 8) * 68 + kk]);
        CVT_TF32(A2, h2e[rA * 68 + kk + 4]);
        CVT_TF32(A3, h2e[(rA + 8) * 68 + kk + 4]);
        const float2* bp = (const float2*)(g_W3t + ((ks << 7) + (w << 3)) * 64) + lane;
        #pragma unroll
        for (int ti = 0; ti < 8; ti++) {
            float2 bv = bp[ti * 32];
            unsigned B0 = __float_as_uint(bv.x);
            unsigned B1 = __float_as_uint(bv.y);
            MMA_TF32(dacc[ti], A0, A1, A2, A3, B0, B1);
        }
    }

    // apply mappings (256 active threads, 4 batches x 4 co per thread)
    const int ea  = t >> 5;              // edge within sub (0..7) for t<256
    const int b0  = ((t >> 3) & 3) * 4;  // 4 batches
    const int j0  = (t & 7) * 4;         // 4 consecutive co

    #pragma unroll
    for (int sub = 0; sub < 2; sub++) {
        const int es0 = sub * 8;

        // staged gather of 8 edges: g[e][b][ci] (all 512 threads)
        #pragma unroll
        for (int r = 0; r < 8; r++) {
            int i  = t + 512 * r;             // 0..4095
            int p8 = i >> 4;                  // (e,ci) 0..255
            int b  = i & 15;
            int e  = p8 >> 5, ci = p8 & 31;
            float v = (es0 + e < net) ? g_featT2[goff[(es0 + e) * 32 + ci] + b] : 0.f;
            g_s[e * 576 + b * 36 + ci] = v;
        }
        // store this sub's filters from D fragments:
        // sub 0 -> rows rA (c0,c1); sub 1 -> rows rA+8 (c2,c3), local edge = rA
        #pragma unroll
        for (int ti = 0; ti < 8; ti++) {
            int col = (w << 6) + ti * 8 + tig * 2;
            int ci  = col >> 5, co = col & 31;
            float2 v;
            v.x = dacc[ti][sub * 2];
            v.y = dacc[ti][sub * 2 + 1];
            *(float2*)&f_s[rA * 1152 + ci * 36 + co] = v;
        }
        __syncthreads();

        // apply (f32x2): 4 batches x 4 co, one edge, threads t<256
        u64 aB[4][2] = {{0ull,0ull},{0ull,0ull},{0ull,0ull},{0ull,0ull}};
        const bool do_apply = (t < 256) && (es0 + ea < net);
        if (do_apply) {
            const float* gp = &g_s[ea * 576 + b0 * 36];
            const unsigned fpa = smb + (OFF_F + ea * 1152 + j0) * 4;
            #pragma unroll
            for (int ci4 = 0; ci4 < 32; ci4 += 4) {
                float4 gv0 = *(const float4*)&gp[ci4];
                float4 gv1 = *(const float4*)&gp[36 + ci4];
                float4 gv2 = *(const float4*)&gp[72 + ci4];
                float4 gv3 = *(const float4*)&gp[108 + ci4];
                float gm[4][4] = {
                    {gv0.x, gv0.y, gv0.z, gv0.w},
                    {gv1.x, gv1.y, gv1.z, gv1.w},
                    {gv2.x, gv2.y, gv2.z, gv2.w},
                    {gv3.x, gv3.y, gv3.z, gv3.w}};
                #pragma unroll
                for (int kk = 0; kk < 4; kk++) {
                    u64 f01, f23;
                    LDS_V2B64(f01, f23, fpa + (ci4 + kk) * 144);
                    #pragma unroll
                    for (int bb = 0; bb < 4; bb++) {
                        u64 d; PACK2(d, gm[bb][kk], gm[bb][kk]);
                        FMA2(aB[bb][0], d, f01, aB[bb][0]);
                        FMA2(aB[bb][1], d, f23, aB[bb][1]);
                    }
                }
            }
        }
        __syncthreads();   // all reads of g_s / f_s complete

        // dump vals to smem (overlay g_s): vals[b][ea*32 + j0 .. +3]
        if (do_apply) {
            #pragma unroll
            for (int bb = 0; bb < 4; bb++) {
                ulonglong2 s2; s2.x = aB[bb][0]; s2.y = aB[bb][1];
                *(ulonglong2*)&vals_s[(b0 + bb) * VROW + ea * 32 + j0] = s2;
            }
        }
        __syncthreads();   // vals ready

        // segment reduce: one (b, group) per task -> single atomicAdd
        {
            const int ng = ng_s[sub];
            const int base = sub * 256;
            for (int task = t; task < 16 * ng; task += 512) {
                int b  = task / ng;
                int gi = task - b * ng;
                int p0 = gst[sub * 66 + gi];
                int p1 = gst[sub * 66 + gi + 1];
                int key = keys_s[p0];
                if (key >= 0) {
                    const float* vp = &vals_s[b * VROW - base];
                    float s = 0.f;
                    for (int p = p0; p < p1; p++) s += vp[p];
                    atomicAdd(&out[(size_t)b * 32768 + key], s);
                }
            }
        }
        __syncthreads();   // before next sub overwrites vals/g_s
    }
}

extern "C" void kernel_launch(void* const* d_in, const int* in_sizes, int n_in,
                              void* d_out, int out_size) {
    const float* features  = (const float*)d_in[0];
    const float* W1        = (const float*)d_in[1];
    const float* W2        = (const float*)d_in[2];
    const float* W3        = (const float*)d_in[3];
    const float* eval_locs = (const float*)d_in[4];
    const int*   eval_idx  = (const int*)d_in[5];
    float*       out       = (float*)d_out;

    const int E = in_sizes[4] / 2;

    cudaFuncSetAttribute(quad_main, cudaFuncAttributeMaxDynamicSharedMemorySize,
                         SMEM_A_BYTES);

    int prep_items = E > (BATCH * 32 * N_OUT) / 4 ? E : (BATCH * 32 * N_OUT) / 4;
    prep_idx<<<(prep_items + 255) / 256, 256>>>(eval_idx, (float4*)out, E);
    prep_w3t<<<256, 256>>>(W3);
    prep_featT<<<dim3(N_IN / 32, 512 / 32), dim3(32, 8)>>>(features);
    quad_main<<<(E + 15) / 16, 512, SMEM_A_BYTES>>>(
        W1, W2, eval_locs, out, E);
}